// round 6
// baseline (speedup 1.0000x reference)
#include <cuda_runtime.h>
#include <cuda_bf16.h>
#include <math.h>
#include <stdint.h>

// ---------------- problem constants ----------------
#define BB     16
#define C_IN   384
#define HW     1024
#define CMID   1536
#define EMB_N  1024
#define NGROUP 32
#define CPG    (C_IN / NGROUP)
#define GSIZE  (CPG * HW)
#define KP1    (3 * C_IN)    // 1152  (split-bf16 K-concat)
#define KP2    (3 * CMID)    // 4608

// ---------------- scratch (global bss) ----------------
__device__ float g_a[BB * C_IN];
__device__ float g_d[BB * C_IN];
__device__ float g_emb[BB * 2 * CMID];
// A' = [hi | hi | lo], rows = output channel, K-contiguous
__device__ __align__(16) __nv_bfloat16 g_w1s[CMID * KP1];
__device__ __align__(16) __nv_bfloat16 g_w2s[C_IN * KP2];
// B' = [hi | lo | hi], rows = pixel p, K-contiguous
__device__ __align__(16) __nv_bfloat16 g_xs[(size_t)BB * HW * KP1];
__device__ __align__(16) __nv_bfloat16 g_hs[(size_t)BB * HW * KP2];

__device__ __forceinline__ uint32_t smem_u32(const void* p) {
    uint32_t a;
    asm("{ .reg .u64 t; cvta.to.shared.u64 t, %1; cvt.u32.u64 %0, t; }" : "=r"(a) : "l"(p));
    return a;
}
__device__ __forceinline__ void ldsm4(uint32_t* r, uint32_t addr) {
    asm volatile("ldmatrix.sync.aligned.m8n8.x4.shared.b16 {%0,%1,%2,%3}, [%4];"
                 : "=r"(r[0]), "=r"(r[1]), "=r"(r[2]), "=r"(r[3]) : "r"(addr));
}
__device__ __forceinline__ void mma16816(float* d, const uint32_t* a, const uint32_t* b) {
    asm volatile("mma.sync.aligned.m16n8k16.row.col.f32.bf16.bf16.f32 "
                 "{%0,%1,%2,%3}, {%4,%5,%6,%7}, {%8,%9}, {%0,%1,%2,%3};"
                 : "+f"(d[0]), "+f"(d[1]), "+f"(d[2]), "+f"(d[3])
                 : "r"(a[0]), "r"(a[1]), "r"(a[2]), "r"(a[3]), "r"(b[0]), "r"(b[1]));
}
__device__ __forceinline__ uint32_t pack_hilo(float r) {
    __nv_bfloat16 h = __float2bfloat16(r);
    __nv_bfloat16 l = __float2bfloat16(r - __bfloat162float(h));
    return (uint32_t)__bfloat16_as_ushort(h) | ((uint32_t)__bfloat16_as_ushort(l) << 16);
}

// ---------------- kernel 1: groupnorm stats ----------------
__global__ __launch_bounds__(256) void gn_stats_kernel(const float* __restrict__ x,
                                                       const float* __restrict__ gn_w,
                                                       const float* __restrict__ gn_b) {
    int g = blockIdx.x, b = g / NGROUP, grp = g % NGROUP;
    const float4* base = (const float4*)(x + ((size_t)b * C_IN + grp * CPG) * HW);
    float s = 0.f, ss = 0.f;
    for (int i = threadIdx.x; i < GSIZE / 4; i += 256) {
        float4 v = base[i];
        s += v.x + v.y + v.z + v.w;
        ss += v.x * v.x + v.y * v.y + v.z * v.z + v.w * v.w;
    }
    for (int o = 16; o; o >>= 1) {
        s  += __shfl_down_sync(0xffffffffu, s, o);
        ss += __shfl_down_sync(0xffffffffu, ss, o);
    }
    __shared__ float rs[8], rss[8], smu, srstd;
    int warp = threadIdx.x >> 5, lane = threadIdx.x & 31;
    if (lane == 0) { rs[warp] = s; rss[warp] = ss; }
    __syncthreads();
    if (threadIdx.x == 0) {
        float ts = 0.f, tss = 0.f;
        #pragma unroll
        for (int w = 0; w < 8; w++) { ts += rs[w]; tss += rss[w]; }
        float mu = ts / (float)GSIZE;
        smu = mu;
        srstd = rsqrtf(tss / (float)GSIZE - mu * mu + 1e-5f);
    }
    __syncthreads();
    if (threadIdx.x < CPG) {
        int c = grp * CPG + threadIdx.x;
        float a = srstd * gn_w[c];
        g_a[b * C_IN + c] = a;
        g_d[b * C_IN + c] = gn_b[c] - smu * a;
    }
}

// ---------------- kernel 2: emb GEMM ----------------
__global__ __launch_bounds__(256) void emb_gemm_kernel(const float* __restrict__ emb,
                                                       const float* __restrict__ we,
                                                       const float* __restrict__ be) {
    int b = blockIdx.x, o = blockIdx.y * 8 + (threadIdx.x >> 5), lane = threadIdx.x & 31;
    __shared__ float4 semb[EMB_N / 4];
    const float4* er = (const float4*)(emb + (size_t)b * EMB_N);
    for (int i = threadIdx.x; i < EMB_N / 4; i += 256) semb[i] = er[i];
    __syncthreads();
    const float4* wr = (const float4*)(we + (size_t)o * EMB_N);
    float s = 0.f;
    #pragma unroll
    for (int i = lane; i < EMB_N / 4; i += 32) {
        float4 a = semb[i], w = wr[i];
        s += a.x * w.x + a.y * w.y + a.z * w.z + a.w * w.w;
    }
    for (int off = 16; off; off >>= 1) s += __shfl_down_sync(0xffffffffu, s, off);
    if (lane == 0) g_emb[(size_t)b * 2 * CMID + o] = s + be[o];
}

// ---------------- kernel 3: weights -> split-bf16 K-concat [hi|hi|lo] ----------------
__global__ __launch_bounds__(256) void prep_w_kernel(const float* __restrict__ w1,
                                                     const float* __restrict__ w2) {
    int i = blockIdx.x * 256 + threadIdx.x;
    if (i < CMID * C_IN) {
        {
            float v = w1[i];
            int m = i / C_IN, c = i % C_IN;
            __nv_bfloat16 h = __float2bfloat16(v);
            __nv_bfloat16 l = __float2bfloat16(v - __bfloat162float(h));
            g_w1s[m * KP1 + c] = h;
            g_w1s[m * KP1 + C_IN + c] = h;
            g_w1s[m * KP1 + 2 * C_IN + c] = l;
        }
        {
            float v = w2[i];
            int m = i / CMID, c = i % CMID;
            __nv_bfloat16 h = __float2bfloat16(v);
            __nv_bfloat16 l = __float2bfloat16(v - __bfloat162float(h));
            g_w2s[m * KP2 + c] = h;
            g_w2s[m * KP2 + CMID + c] = h;
            g_w2s[m * KP2 + 2 * CMID + c] = l;
        }
    }
}

// ---------------- kernel 4: xn^T split-bf16 [hi|lo|hi] (GN affine + transpose) ----------------
__global__ __launch_bounds__(256) void prep_x_kernel(const float* __restrict__ x) {
    __shared__ float sm[32][33];
    int p0 = blockIdx.x * 32, c0 = blockIdx.y * 32, b = blockIdx.z;
    int tx = threadIdx.x & 31, ty = threadIdx.x >> 5;
    #pragma unroll
    for (int i = 0; i < 4; i++) {
        int c = c0 + ty + 8 * i;
        float av = g_a[b * C_IN + c], dv = g_d[b * C_IN + c];
        sm[ty + 8 * i][tx] = fmaf(x[((size_t)b * C_IN + c) * HW + p0 + tx], av, dv);
    }
    __syncthreads();
    #pragma unroll
    for (int i = 0; i < 4; i++) {
        int p = p0 + ty + 8 * i;
        float v = sm[tx][ty + 8 * i];
        __nv_bfloat16 h = __float2bfloat16(v);
        __nv_bfloat16 l = __float2bfloat16(v - __bfloat162float(h));
        size_t o = ((size_t)b * HW + p) * KP1 + c0 + tx;
        g_xs[o] = h;
        g_xs[o + C_IN] = l;
        g_xs[o + 2 * C_IN] = h;
    }
}

// ---------------- kernels 5/6: bf16 mma.sync GEMM (split-bf16 via K-concat) ----------------
// D[m,n] = sum_k A'[m,k] B'[n,k].  BM=BN=128, BK=32, 512 thr (16 warps, tile 64x16).
// MODE 0: K'=1152, epi: bias+silu+modulate -> g_hs [hi|lo|hi]
// MODE 1: K'=4608, epi: bias+residual -> fp32 out
#define SMEM_BYTES (128 * 132 * 4)   // 67584; mainloop uses first 40960
template <int MODE>
__global__ __launch_bounds__(512) void mma_gemm(const float* __restrict__ bias,
                                                const float* __restrict__ xres,
                                                float* __restrict__ out) {
    constexpr int KP  = (MODE == 0) ? KP1 : KP2;
    constexpr int NCH = KP / 32;

    extern __shared__ __align__(16) char smem[];
    const uint32_t sb = smem_u32(smem);

    const int t = threadIdx.x, lane = t & 31, warp = t >> 5;
    const int wm = warp & 1, wn = warp >> 1;            // warp tile: 64(m) x 16(n)
    const int b = blockIdx.z, bm = blockIdx.y * 128, bn = blockIdx.x * 128;

    const __nv_bfloat16* __restrict__ Ag = (MODE == 0) ? g_w1s : g_w2s;
    const __nv_bfloat16* __restrict__ Bg = ((MODE == 0) ? g_xs : g_hs) + (size_t)b * HW * KP;

    // global staging: 512 uint4 per tile, 1 per thread
    const int lrow = t >> 2, lseg = t & 3;
    const __nv_bfloat16* __restrict__ aptr = Ag + (size_t)(bm + lrow) * KP + lseg * 8;
    const __nv_bfloat16* __restrict__ bptr = Bg + (size_t)(bn + lrow) * KP + lseg * 8;
    const uint32_t sts_off = lrow * 80 + lseg * 16;     // row stride 80 B (40 bf16, padded)

    // ldmatrix lane offsets (stride 80 B -> all-32-bank conflict-free phases)
    const uint32_t a_off = (uint32_t)((wm * 64 + (lane & 15)) * 80 + (lane >> 4) * 16);
    const uint32_t b_off = (uint32_t)((wn * 16 + (lane & 7) + ((lane >> 4) & 1) * 8) * 80
                                      + ((lane >> 3) & 1) * 16);

    float acc[4][2][4];
    #pragma unroll
    for (int i = 0; i < 4; i++)
        #pragma unroll
        for (int j = 0; j < 2; j++)
            #pragma unroll
            for (int q = 0; q < 4; q++) acc[i][j][q] = 0.f;

    uint4 ra, rb;
    auto ldg = [&](int k0) {
        ra = *(const uint4*)(aptr + k0);
        rb = *(const uint4*)(bptr + k0);
    };
    auto sts = [&](int buf) {
        uint32_t sa = sb + buf * 10240 + sts_off;
        uint32_t sbB = sb + 20480 + buf * 10240 + sts_off;
        asm volatile("st.shared.v4.b32 [%0], {%1,%2,%3,%4};" ::
                     "r"(sa), "r"(ra.x), "r"(ra.y), "r"(ra.z), "r"(ra.w) : "memory");
        asm volatile("st.shared.v4.b32 [%0], {%1,%2,%3,%4};" ::
                     "r"(sbB), "r"(rb.x), "r"(rb.y), "r"(rb.z), "r"(rb.w) : "memory");
    };

    ldg(0);
    sts(0);
    __syncthreads();

    for (int ch = 0; ch < NCH; ch++) {
        const int cur = ch & 1;
        if (ch + 1 < NCH) ldg((ch + 1) * 32);   // prefetch next chunk under compute

        const uint32_t sa = sb + cur * 10240;
        const uint32_t sbb = sb + 20480 + cur * 10240;
        #pragma unroll
        for (int s16 = 0; s16 < 2; s16++) {
            uint32_t A[4][4], Bv[4];
            #pragma unroll
            for (int mi = 0; mi < 4; mi++)
                ldsm4(A[mi], sa + a_off + mi * 1280 + s16 * 32);
            ldsm4(Bv, sbb + b_off + s16 * 32);
            #pragma unroll
            for (int mi = 0; mi < 4; mi++) {
                mma16816(acc[mi][0], A[mi], Bv);
                mma16816(acc[mi][1], A[mi], Bv + 2);
            }
        }

        if (ch + 1 < NCH) {
            sts(cur ^ 1);
            __syncthreads();
        }
    }
    __syncthreads();   // smem now reused for epilogue transpose

    uint32_t* smt = (uint32_t*)smem;   // [128][132]
    if (MODE == 0) {
        // per-thread m values: wm*64 + mi*16 + (lane>>2) + {0,8}
        float bsv[8], scv[8], shv[8];
        #pragma unroll
        for (int mi = 0; mi < 4; mi++) {
            #pragma unroll
            for (int hh = 0; hh < 2; hh++) {
                int m = bm + wm * 64 + mi * 16 + (lane >> 2) + hh * 8;
                bsv[mi * 2 + hh] = bias[m];
                scv[mi * 2 + hh] = 1.f + g_emb[(size_t)b * 2 * CMID + m];
                shv[mi * 2 + hh] = g_emb[(size_t)b * 2 * CMID + CMID + m];
            }
        }
        #pragma unroll
        for (int mi = 0; mi < 4; mi++) {
            #pragma unroll
            for (int nj = 0; nj < 2; nj++) {
                int n0 = wn * 16 + nj * 8 + 2 * (lane & 3);
                #pragma unroll
                for (int q = 0; q < 4; q++) {
                    int hh = q >> 1;                       // c0,c1 -> m; c2,c3 -> m+8
                    int mloc = wm * 64 + mi * 16 + (lane >> 2) + hh * 8;
                    int n = n0 + (q & 1);
                    float v = acc[mi][nj][q] + bsv[mi * 2 + hh];
                    float s = v / (1.f + __expf(-v));
                    float r = fmaf(s, scv[mi * 2 + hh], shv[mi * 2 + hh]);
                    smt[n * 132 + mloc] = pack_hilo(r);
                }
            }
        }
        __syncthreads();
        // write h' rows: [hi | lo | hi], thread: n = t>>2, m-segment (t&3)*32
        const int n = t >> 2, mseg = (t & 3) * 32;
        const size_t rowb = ((size_t)b * HW + bn + n) * KP2;
        #pragma unroll
        for (int j = 0; j < 4; j++) {
            uint32_t w[8];
            #pragma unroll
            for (int q = 0; q < 8; q++) w[q] = smt[n * 132 + mseg + 8 * j + q];
            uint4 vh, vl;
            vh.x = (w[0] & 0xFFFFu) | (w[1] << 16);
            vh.y = (w[2] & 0xFFFFu) | (w[3] << 16);
            vh.z = (w[4] & 0xFFFFu) | (w[5] << 16);
            vh.w = (w[6] & 0xFFFFu) | (w[7] << 16);
            vl.x = (w[0] >> 16) | (w[1] & 0xFFFF0000u);
            vl.y = (w[2] >> 16) | (w[3] & 0xFFFF0000u);
            vl.z = (w[4] >> 16) | (w[5] & 0xFFFF0000u);
            vl.w = (w[6] >> 16) | (w[7] & 0xFFFF0000u);
            int col = bm + mseg + 8 * j;
            *(uint4*)(g_hs + rowb + col) = vh;
            *(uint4*)(g_hs + rowb + CMID + col) = vl;
            *(uint4*)(g_hs + rowb + 2 * CMID + col) = vh;
        }
    } else {
        // stage raw acc transposed: smt[m][n]
        #pragma unroll
        for (int mi = 0; mi < 4; mi++) {
            #pragma unroll
            for (int nj = 0; nj < 2; nj++) {
                int n0 = wn * 16 + nj * 8 + 2 * (lane & 3);
                #pragma unroll
                for (int q = 0; q < 4; q++) {
                    int mloc = wm * 64 + mi * 16 + (lane >> 2) + (q >> 1) * 8;
                    int n = n0 + (q & 1);
                    smt[mloc * 132 + n] = __float_as_uint(acc[mi][nj][q]);
                }
            }
        }
        __syncthreads();
        const int m = t >> 2, nseg = (t & 3) * 32;
        const float bs = bias[bm + m];
        const size_t rowb = ((size_t)(b * C_IN + bm + m)) * HW + bn + nseg;
        #pragma unroll
        for (int j = 0; j < 8; j++) {
            float4 xr = *(const float4*)&xres[rowb + 4 * j];
            float4 o;
            o.x = __uint_as_float(smt[m * 132 + nseg + 4 * j + 0]) + bs + xr.x;
            o.y = __uint_as_float(smt[m * 132 + nseg + 4 * j + 1]) + bs + xr.y;
            o.z = __uint_as_float(smt[m * 132 + nseg + 4 * j + 2]) + bs + xr.z;
            o.w = __uint_as_float(smt[m * 132 + nseg + 4 * j + 3]) + bs + xr.w;
            *(float4*)&out[rowb + 4 * j] = o;
        }
    }
}

// ---------------- launch ----------------
extern "C" void kernel_launch(void* const* d_in, const int* in_sizes, int n_in,
                              void* d_out, int out_size) {
    const float* x    = (const float*)d_in[0];
    const float* emb  = (const float*)d_in[1];
    const float* gn_w = (const float*)d_in[2];
    const float* gn_b = (const float*)d_in[3];
    const float* w1   = (const float*)d_in[4];
    const float* b1   = (const float*)d_in[5];
    const float* we   = (const float*)d_in[6];
    const float* be   = (const float*)d_in[7];
    const float* w2   = (const float*)d_in[8];
    const float* b2   = (const float*)d_in[9];
    float* out = (float*)d_out;

    cudaFuncSetAttribute(mma_gemm<0>, cudaFuncAttributeMaxDynamicSharedMemorySize, SMEM_BYTES);
    cudaFuncSetAttribute(mma_gemm<1>, cudaFuncAttributeMaxDynamicSharedMemorySize, SMEM_BYTES);

    gn_stats_kernel<<<BB * NGROUP, 256>>>(x, gn_w, gn_b);
    emb_gemm_kernel<<<dim3(BB, (2 * CMID) / 8), 256>>>(emb, we, be);
    prep_w_kernel<<<(CMID * C_IN + 255) / 256, 256>>>(w1, w2);
    prep_x_kernel<<<dim3(HW / 32, C_IN / 32, BB), 256>>>(x);
    mma_gemm<0><<<dim3(HW / 128, CMID / 128, BB), 512, SMEM_BYTES>>>(b1, nullptr, nullptr);
    mma_gemm<1><<<dim3(HW / 128, C_IN / 128, BB), 512, SMEM_BYTES>>>(b2, x, out);
}

// round 9
// speedup vs baseline: 1.1960x; 1.1960x over previous
#include <cuda_runtime.h>
#include <cuda_bf16.h>
#include <math.h>
#include <stdint.h>

// ---------------- problem constants ----------------
#define BB     16
#define C_IN   384
#define HW     1024
#define CMID   1536
#define EMB_N  1024
#define NGROUP 32
#define CPG    (C_IN / NGROUP)
#define GSIZE  (CPG * HW)

// ---------------- scratch (global bss) ----------------
__device__ float g_a[BB * C_IN];
__device__ float g_d[BB * C_IN];
__device__ float g_emb[BB * 2 * CMID];
// split-bf16 stored as [hi | lo] (K-concat segments remapped at load time)
__device__ __align__(16) __nv_bfloat16 g_w1s[CMID * 2 * C_IN];
__device__ __align__(16) __nv_bfloat16 g_w2s[C_IN * 2 * CMID];
__device__ __align__(16) __nv_bfloat16 g_xs[(size_t)BB * HW * 2 * C_IN];
__device__ __align__(16) __nv_bfloat16 g_hs[(size_t)BB * HW * 2 * CMID];

__device__ __forceinline__ uint32_t smem_u32(const void* p) {
    uint32_t a;
    asm("{ .reg .u64 t; cvta.to.shared.u64 t, %1; cvt.u32.u64 %0, t; }" : "=r"(a) : "l"(p));
    return a;
}
__device__ __forceinline__ void ldsm4(uint32_t* r, uint32_t addr) {
    asm volatile("ldmatrix.sync.aligned.m8n8.x4.shared.b16 {%0,%1,%2,%3}, [%4];"
                 : "=r"(r[0]), "=r"(r[1]), "=r"(r[2]), "=r"(r[3]) : "r"(addr));
}
__device__ __forceinline__ void mma16816(float* d, const uint32_t* a, const uint32_t* b) {
    asm volatile("mma.sync.aligned.m16n8k16.row.col.f32.bf16.bf16.f32 "
                 "{%0,%1,%2,%3}, {%4,%5,%6,%7}, {%8,%9}, {%0,%1,%2,%3};"
                 : "+f"(d[0]), "+f"(d[1]), "+f"(d[2]), "+f"(d[3])
                 : "r"(a[0]), "r"(a[1]), "r"(a[2]), "r"(a[3]), "r"(b[0]), "r"(b[1]));
}
__device__ __forceinline__ uint32_t pack_hilo(float r) {
    __nv_bfloat16 h = __float2bfloat16(r);
    __nv_bfloat16 l = __float2bfloat16(r - __bfloat162float(h));
    return (uint32_t)__bfloat16_as_ushort(h) | ((uint32_t)__bfloat16_as_ushort(l) << 16);
}
#define CP_ASYNC16(dst, src) \
    asm volatile("cp.async.cg.shared.global [%0], [%1], 16;" :: "r"(dst), "l"(src) : "memory")
#define CP_COMMIT() asm volatile("cp.async.commit_group;" ::: "memory")
#define CP_WAIT1()  asm volatile("cp.async.wait_group 1;" ::: "memory")

// ---------------- kernel 1: groupnorm stats ----------------
__global__ __launch_bounds__(256) void gn_stats_kernel(const float* __restrict__ x,
                                                       const float* __restrict__ gn_w,
                                                       const float* __restrict__ gn_b) {
    int g = blockIdx.x, b = g / NGROUP, grp = g % NGROUP;
    const float4* base = (const float4*)(x + ((size_t)b * C_IN + grp * CPG) * HW);
    float s = 0.f, ss = 0.f;
    for (int i = threadIdx.x; i < GSIZE / 4; i += 256) {
        float4 v = base[i];
        s += v.x + v.y + v.z + v.w;
        ss += v.x * v.x + v.y * v.y + v.z * v.z + v.w * v.w;
    }
    for (int o = 16; o; o >>= 1) {
        s  += __shfl_down_sync(0xffffffffu, s, o);
        ss += __shfl_down_sync(0xffffffffu, ss, o);
    }
    __shared__ float rs[8], rss[8], smu, srstd;
    int warp = threadIdx.x >> 5, lane = threadIdx.x & 31;
    if (lane == 0) { rs[warp] = s; rss[warp] = ss; }
    __syncthreads();
    if (threadIdx.x == 0) {
        float ts = 0.f, tss = 0.f;
        #pragma unroll
        for (int w = 0; w < 8; w++) { ts += rs[w]; tss += rss[w]; }
        float mu = ts / (float)GSIZE;
        smu = mu;
        srstd = rsqrtf(tss / (float)GSIZE - mu * mu + 1e-5f);
    }
    __syncthreads();
    if (threadIdx.x < CPG) {
        int c = grp * CPG + threadIdx.x;
        float a = srstd * gn_w[c];
        g_a[b * C_IN + c] = a;
        g_d[b * C_IN + c] = gn_b[c] - smu * a;
    }
}

// ---------------- kernel 2: emb GEMM ----------------
__global__ __launch_bounds__(256) void emb_gemm_kernel(const float* __restrict__ emb,
                                                       const float* __restrict__ we,
                                                       const float* __restrict__ be) {
    int b = blockIdx.x, o = blockIdx.y * 8 + (threadIdx.x >> 5), lane = threadIdx.x & 31;
    __shared__ float4 semb[EMB_N / 4];
    const float4* er = (const float4*)(emb + (size_t)b * EMB_N);
    for (int i = threadIdx.x; i < EMB_N / 4; i += 256) semb[i] = er[i];
    __syncthreads();
    const float4* wr = (const float4*)(we + (size_t)o * EMB_N);
    float s = 0.f;
    #pragma unroll
    for (int i = lane; i < EMB_N / 4; i += 32) {
        float4 a = semb[i], w = wr[i];
        s += a.x * w.x + a.y * w.y + a.z * w.z + a.w * w.w;
    }
    for (int off = 16; off; off >>= 1) s += __shfl_down_sync(0xffffffffu, s, off);
    if (lane == 0) g_emb[(size_t)b * 2 * CMID + o] = s + be[o];
}

// ---------------- kernel 3: weights -> split-bf16 [hi|lo] ----------------
__global__ __launch_bounds__(256) void prep_w_kernel(const float* __restrict__ w1,
                                                     const float* __restrict__ w2) {
    int i = blockIdx.x * 256 + threadIdx.x;
    if (i < CMID * C_IN) {
        {
            float v = w1[i];
            int m = i / C_IN, c = i % C_IN;
            __nv_bfloat16 h = __float2bfloat16(v);
            g_w1s[m * 2 * C_IN + c] = h;
            g_w1s[m * 2 * C_IN + C_IN + c] = __float2bfloat16(v - __bfloat162float(h));
        }
        {
            float v = w2[i];
            int m = i / CMID, c = i % CMID;
            __nv_bfloat16 h = __float2bfloat16(v);
            g_w2s[m * 2 * CMID + c] = h;
            g_w2s[m * 2 * CMID + CMID + c] = __float2bfloat16(v - __bfloat162float(h));
        }
    }
}

// ---------------- kernel 4: xn^T split-bf16 [hi|lo] (GN affine + transpose) ----------------
__global__ __launch_bounds__(256) void prep_x_kernel(const float* __restrict__ x) {
    __shared__ float sm[32][33];
    int p0 = blockIdx.x * 32, c0 = blockIdx.y * 32, b = blockIdx.z;
    int tx = threadIdx.x & 31, ty = threadIdx.x >> 5;
    #pragma unroll
    for (int i = 0; i < 4; i++) {
        int c = c0 + ty + 8 * i;
        float av = g_a[b * C_IN + c], dv = g_d[b * C_IN + c];
        sm[ty + 8 * i][tx] = fmaf(x[((size_t)b * C_IN + c) * HW + p0 + tx], av, dv);
    }
    __syncthreads();
    #pragma unroll
    for (int i = 0; i < 4; i++) {
        int p = p0 + ty + 8 * i;
        float v = sm[tx][ty + 8 * i];
        __nv_bfloat16 h = __float2bfloat16(v);
        size_t o = ((size_t)b * HW + p) * 2 * C_IN + c0 + tx;
        g_xs[o] = h;
        g_xs[o + C_IN] = __float2bfloat16(v - __bfloat162float(h));
    }
}

// ---------------- kernels 5/6: bf16 mma.sync GEMM, 3-stage cp.async pipeline ----------------
// Logical K' = 3*Kbase: chunk ch -> segment s = ch/cps; A reads [hi,hi,lo], B reads [hi,lo,hi].
// BM=BN=128, BK=32, 512 thr (16 warps, warp tile 64x16).
// MODE 0: Kbase=384,  epi: bias+silu+modulate -> g_hs [hi|lo]
// MODE 1: Kbase=1536, epi: bias+residual -> fp32 out
#define STAGE_BYTES 20480            // A 128x80B + B 128x80B
#define SMEM_BYTES  (128 * 132 * 4)  // 67584 >= 3*STAGE_BYTES (61440)
template <int MODE>
__global__ __launch_bounds__(512) void mma_gemm(const float* __restrict__ bias,
                                                const float* __restrict__ xres,
                                                float* __restrict__ out) {
    constexpr int Kb  = (MODE == 0) ? C_IN : CMID;
    constexpr int cps = Kb / 32;
    constexpr int NCH = 3 * cps;

    extern __shared__ __align__(16) char smem[];
    const uint32_t sb = smem_u32(smem);

    const int t = threadIdx.x, lane = t & 31, warp = t >> 5;
    const int wm = warp & 1, wn = warp >> 1;
    const int b = blockIdx.z, bm = blockIdx.y * 128, bn = blockIdx.x * 128;

    const __nv_bfloat16* __restrict__ Ag = (MODE == 0) ? g_w1s : g_w2s;
    const __nv_bfloat16* __restrict__ Bg =
        ((MODE == 0) ? g_xs : g_hs) + (size_t)b * HW * 2 * Kb;

    const int lrow = t >> 2, lseg = t & 3;
    const __nv_bfloat16* __restrict__ aptr = Ag + (size_t)(bm + lrow) * 2 * Kb + lseg * 8;
    const __nv_bfloat16* __restrict__ bptr = Bg + (size_t)(bn + lrow) * 2 * Kb + lseg * 8;
    const uint32_t sts_off = lrow * 80 + lseg * 16;   // 80B row stride: conflict-free ldsm

    const uint32_t a_off = (uint32_t)((wm * 64 + (lane & 15)) * 80 + (lane >> 4) * 16);
    const uint32_t b_off = (uint32_t)((wn * 16 + (lane & 7) + ((lane >> 4) & 1) * 8) * 80
                                      + ((lane >> 3) & 1) * 16);

    float acc[4][2][4];
    #pragma unroll
    for (int i = 0; i < 4; i++)
        #pragma unroll
        for (int j = 0; j < 2; j++)
            #pragma unroll
            for (int q = 0; q < 4; q++) acc[i][j][q] = 0.f;

    auto issue = [&](int ch2, int buf) {
        if (ch2 < NCH) {
            int s = ch2 / cps, r = ch2 - s * cps;
            int kA = ((s == 2) ? Kb : 0) + r * 32;   // A segments: hi, hi, lo
            int kB = ((s == 1) ? Kb : 0) + r * 32;   // B segments: hi, lo, hi
            CP_ASYNC16(sb + buf * STAGE_BYTES + sts_off, aptr + kA);
            CP_ASYNC16(sb + buf * STAGE_BYTES + 10240 + sts_off, bptr + kB);
        }
        CP_COMMIT();
    };

    issue(0, 0);
    issue(1, 1);

    for (int ch = 0; ch < NCH; ch++) {
        CP_WAIT1();
        __syncthreads();
        issue(ch + 2, (ch + 2) % 3);          // overwrites buf (ch-1)%3: safe post-barrier

        const uint32_t sa  = sb + (ch % 3) * STAGE_BYTES;
        const uint32_t sbb = sa + 10240;
        #pragma unroll
        for (int s16 = 0; s16 < 2; s16++) {
            uint32_t A[4][4], Bv[4];
            #pragma unroll
            for (int mi = 0; mi < 4; mi++)
                ldsm4(A[mi], sa + a_off + mi * 1280 + s16 * 32);
            ldsm4(Bv, sbb + b_off + s16 * 32);
            #pragma unroll
            for (int mi = 0; mi < 4; mi++) {
                mma16816(acc[mi][0], A[mi], Bv);
                mma16816(acc[mi][1], A[mi], Bv + 2);
            }
        }
    }
    __syncthreads();   // smem reused for epilogue transpose

    uint32_t* smt = (uint32_t*)smem;   // [128][132]
    if (MODE == 0) {
        float bsv[8], scv[8], shv[8];
        #pragma unroll
        for (int mi = 0; mi < 4; mi++) {
            #pragma unroll
            for (int hh = 0; hh < 2; hh++) {
                int m = bm + wm * 64 + mi * 16 + (lane >> 2) + hh * 8;
                bsv[mi * 2 + hh] = bias[m];
                scv[mi * 2 + hh] = 1.f + g_emb[(size_t)b * 2 * CMID + m];
                shv[mi * 2 + hh] = g_emb[(size_t)b * 2 * CMID + CMID + m];
            }
        }
        #pragma unroll
        for (int mi = 0; mi < 4; mi++) {
            #pragma unroll
            for (int nj = 0; nj < 2; nj++) {
                int n0 = wn * 16 + nj * 8 + 2 * (lane & 3);
                #pragma unroll
                for (int q = 0; q < 4; q++) {
                    int hh = q >> 1;
                    int mloc = wm * 64 + mi * 16 + (lane >> 2) + hh * 8;
                    int n = n0 + (q & 1);
                    float v = acc[mi][nj][q] + bsv[mi * 2 + hh];
                    float s = v / (1.f + __expf(-v));
                    float r = fmaf(s, scv[mi * 2 + hh], shv[mi * 2 + hh]);
                    smt[n * 132 + mloc] = pack_hilo(r);
                }
            }
        }
        __syncthreads();
        const int n = t >> 2, mseg = (t & 3) * 32;
        const size_t rowb = ((size_t)b * HW + bn + n) * 2 * CMID;
        #pragma unroll
        for (int j = 0; j < 4; j++) {
            uint32_t w[8];
            #pragma unroll
            for (int q = 0; q < 8; q++) w[q] = smt[n * 132 + mseg + 8 * j + q];
            uint4 vh, vl;
            vh.x = (w[0] & 0xFFFFu) | (w[1] << 16);
            vh.y = (w[2] & 0xFFFFu) | (w[3] << 16);
            vh.z = (w[4] & 0xFFFFu) | (w[5] << 16);
            vh.w = (w[6] & 0xFFFFu) | (w[7] << 16);
            vl.x = (w[0] >> 16) | (w[1] & 0xFFFF0000u);
            vl.y = (w[2] >> 16) | (w[3] & 0xFFFF0000u);
            vl.z = (w[4] >> 16) | (w[5] & 0xFFFF0000u);
            vl.w = (w[6] >> 16) | (w[7] & 0xFFFF0000u);
            int col = bm + mseg + 8 * j;
            *(uint4*)(g_hs + rowb + col) = vh;
            *(uint4*)(g_hs + rowb + CMID + col) = vl;
        }
    } else {
        #pragma unroll
        for (int mi = 0; mi < 4; mi++) {
            #pragma unroll
            for (int nj = 0; nj < 2; nj++) {
                int n0 = wn * 16 + nj * 8 + 2 * (lane & 3);
                #pragma unroll
                for (int q = 0; q < 4; q++) {
                    int mloc = wm * 64 + mi * 16 + (lane >> 2) + (q >> 1) * 8;
                    int n = n0 + (q & 1);
                    smt[mloc * 132 + n] = __float_as_uint(acc[mi][nj][q]);
                }
            }
        }
        __syncthreads();
        const int m = t >> 2, nseg = (t & 3) * 32;
        const float bs = bias[bm + m];
        const size_t rowb = ((size_t)(b * C_IN + bm + m)) * HW + bn + nseg;
        #pragma unroll
        for (int j = 0; j < 8; j++) {
            float4 xr = *(const float4*)&xres[rowb + 4 * j];
            float4 o;
            o.x = __uint_as_float(smt[m * 132 + nseg + 4 * j + 0]) + bs + xr.x;
            o.y = __uint_as_float(smt[m * 132 + nseg + 4 * j + 1]) + bs + xr.y;
            o.z = __uint_as_float(smt[m * 132 + nseg + 4 * j + 2]) + bs + xr.z;
            o.w = __uint_as_float(smt[m * 132 + nseg + 4 * j + 3]) + bs + xr.w;
            *(float4*)&out[rowb + 4 * j] = o;
        }
    }
}

// ---------------- launch ----------------
extern "C" void kernel_launch(void* const* d_in, const int* in_sizes, int n_in,
                              void* d_out, int out_size) {
    const float* x    = (const float*)d_in[0];
    const float* emb  = (const float*)d_in[1];
    const float* gn_w = (const float*)d_in[2];
    const float* gn_b = (const float*)d_in[3];
    const float* w1   = (const float*)d_in[4];
    const float* b1   = (const float*)d_in[5];
    const float* we   = (const float*)d_in[6];
    const float* be   = (const float*)d_in[7];
    const float* w2   = (const float*)d_in[8];
    const float* b2   = (const float*)d_in[9];
    float* out = (float*)d_out;

    cudaFuncSetAttribute(mma_gemm<0>, cudaFuncAttributeMaxDynamicSharedMemorySize, SMEM_BYTES);
    cudaFuncSetAttribute(mma_gemm<1>, cudaFuncAttributeMaxDynamicSharedMemorySize, SMEM_BYTES);

    gn_stats_kernel<<<BB * NGROUP, 256>>>(x, gn_w, gn_b);
    emb_gemm_kernel<<<dim3(BB, (2 * CMID) / 8), 256>>>(emb, we, be);
    prep_w_kernel<<<(CMID * C_IN + 255) / 256, 256>>>(w1, w2);
    prep_x_kernel<<<dim3(HW / 32, C_IN / 32, BB), 256>>>(x);
    mma_gemm<0><<<dim3(HW / 128, CMID / 128, BB), 512, SMEM_BYTES>>>(b1, nullptr, nullptr);
    mma_gemm<1><<<dim3(HW / 128, C_IN / 128, BB), 512, SMEM_BYTES>>>(b2, x, out);
}

// round 15
// speedup vs baseline: 1.8254x; 1.5263x over previous
#include <cuda_runtime.h>
#include <cuda_fp16.h>
#include <math.h>
#include <stdint.h>

// ---------------- problem constants ----------------
#define BB     16
#define C_IN   384
#define HW     1024
#define CMID   1536
#define EMB_N  1024
#define NGROUP 32
#define CPG    (C_IN / NGROUP)
#define GSIZE  (CPG * HW)

// ---------------- scratch (global bss) ----------------
__device__ float g_a[BB * C_IN];
__device__ float g_d[BB * C_IN];
__device__ float g_emb[BB * 2 * CMID];
// weights split fp16 [hi | lo]; activations single fp16
__device__ __align__(16) __half g_w1s[CMID * 2 * C_IN];
__device__ __align__(16) __half g_w2s[C_IN * 2 * CMID];
__device__ __align__(16) __half g_xs[(size_t)BB * HW * C_IN];    // xn^T [b][p][c]
__device__ __align__(16) __half g_hs[(size_t)BB * HW * CMID];    // h^T  [b][p][c]

__device__ __forceinline__ uint32_t smem_u32(const void* p) {
    uint32_t a;
    asm("{ .reg .u64 t; cvta.to.shared.u64 t, %1; cvt.u32.u64 %0, t; }" : "=r"(a) : "l"(p));
    return a;
}
__device__ __forceinline__ void ldsm4(uint32_t* r, uint32_t addr) {
    asm volatile("ldmatrix.sync.aligned.m8n8.x4.shared.b16 {%0,%1,%2,%3}, [%4];"
                 : "=r"(r[0]), "=r"(r[1]), "=r"(r[2]), "=r"(r[3]) : "r"(addr));
}
__device__ __forceinline__ void mma16816(float* d, const uint32_t* a, const uint32_t* b) {
    asm volatile("mma.sync.aligned.m16n8k16.row.col.f32.f16.f16.f32 "
                 "{%0,%1,%2,%3}, {%4,%5,%6,%7}, {%8,%9}, {%0,%1,%2,%3};"
                 : "+f"(d[0]), "+f"(d[1]), "+f"(d[2]), "+f"(d[3])
                 : "r"(a[0]), "r"(a[1]), "r"(a[2]), "r"(a[3]), "r"(b[0]), "r"(b[1]));
}
#define CP_ASYNC16(dst, src) \
    asm volatile("cp.async.cg.shared.global [%0], [%1], 16;" :: "r"(dst), "l"(src) : "memory")
#define CP_COMMIT() asm volatile("cp.async.commit_group;" ::: "memory")
#define CP_WAIT2()  asm volatile("cp.async.wait_group 2;" ::: "memory")

// ---------------- kernel 1: groupnorm stats ----------------
__global__ __launch_bounds__(256) void gn_stats_kernel(const float* __restrict__ x,
                                                       const float* __restrict__ gn_w,
                                                       const float* __restrict__ gn_b) {
    int g = blockIdx.x, b = g / NGROUP, grp = g % NGROUP;
    const float4* base = (const float4*)(x + ((size_t)b * C_IN + grp * CPG) * HW);
    float s = 0.f, ss = 0.f;
    for (int i = threadIdx.x; i < GSIZE / 4; i += 256) {
        float4 v = base[i];
        s += v.x + v.y + v.z + v.w;
        ss += v.x * v.x + v.y * v.y + v.z * v.z + v.w * v.w;
    }
    for (int o = 16; o; o >>= 1) {
        s  += __shfl_down_sync(0xffffffffu, s, o);
        ss += __shfl_down_sync(0xffffffffu, ss, o);
    }
    __shared__ float rs[8], rss[8], smu, srstd;
    int warp = threadIdx.x >> 5, lane = threadIdx.x & 31;
    if (lane == 0) { rs[warp] = s; rss[warp] = ss; }
    __syncthreads();
    if (threadIdx.x == 0) {
        float ts = 0.f, tss = 0.f;
        #pragma unroll
        for (int w = 0; w < 8; w++) { ts += rs[w]; tss += rss[w]; }
        float mu = ts / (float)GSIZE;
        smu = mu;
        srstd = rsqrtf(tss / (float)GSIZE - mu * mu + 1e-5f);
    }
    __syncthreads();
    if (threadIdx.x < CPG) {
        int c = grp * CPG + threadIdx.x;
        float a = srstd * gn_w[c];
        g_a[b * C_IN + c] = a;
        g_d[b * C_IN + c] = gn_b[c] - smu * a;
    }
}

// ---------------- kernel 2: emb GEMM ----------------
__global__ __launch_bounds__(256) void emb_gemm_kernel(const float* __restrict__ emb,
                                                       const float* __restrict__ we,
                                                       const float* __restrict__ be) {
    int b = blockIdx.x, o = blockIdx.y * 8 + (threadIdx.x >> 5), lane = threadIdx.x & 31;
    __shared__ float4 semb[EMB_N / 4];
    const float4* er = (const float4*)(emb + (size_t)b * EMB_N);
    for (int i = threadIdx.x; i < EMB_N / 4; i += 256) semb[i] = er[i];
    __syncthreads();
    const float4* wr = (const float4*)(we + (size_t)o * EMB_N);
    float s = 0.f;
    #pragma unroll
    for (int i = lane; i < EMB_N / 4; i += 32) {
        float4 a = semb[i], w = wr[i];
        s += a.x * w.x + a.y * w.y + a.z * w.z + a.w * w.w;
    }
    for (int off = 16; off; off >>= 1) s += __shfl_down_sync(0xffffffffu, s, off);
    if (lane == 0) g_emb[(size_t)b * 2 * CMID + o] = s + be[o];
}

// ---------------- kernel 3: weights -> split-fp16 [hi|lo] ----------------
__global__ __launch_bounds__(256) void prep_w_kernel(const float* __restrict__ w1,
                                                     const float* __restrict__ w2) {
    int i = blockIdx.x * 256 + threadIdx.x;
    if (i < CMID * C_IN) {
        {
            float v = w1[i];
            int m = i / C_IN, c = i % C_IN;
            __half h = __float2half_rn(v);
            g_w1s[m * 2 * C_IN + c] = h;
            g_w1s[m * 2 * C_IN + C_IN + c] = __float2half_rn(v - __half2float(h));
        }
        {
            float v = w2[i];
            int m = i / CMID, c = i % CMID;
            __half h = __float2half_rn(v);
            g_w2s[m * 2 * CMID + c] = h;
            g_w2s[m * 2 * CMID + CMID + c] = __float2half_rn(v - __half2float(h));
        }
    }
}

// ---------------- kernel 4: xn^T fp16 (GN affine + transpose) ----------------
__global__ __launch_bounds__(256) void prep_x_kernel(const float* __restrict__ x) {
    __shared__ float sm[32][33];
    int p0 = blockIdx.x * 32, c0 = blockIdx.y * 32, b = blockIdx.z;
    int tx = threadIdx.x & 31, ty = threadIdx.x >> 5;
    #pragma unroll
    for (int i = 0; i < 4; i++) {
        int c = c0 + ty + 8 * i;
        float av = g_a[b * C_IN + c], dv = g_d[b * C_IN + c];
        sm[ty + 8 * i][tx] = fmaf(x[((size_t)b * C_IN + c) * HW + p0 + tx], av, dv);
    }
    __syncthreads();
    #pragma unroll
    for (int i = 0; i < 4; i++) {
        int p = p0 + ty + 8 * i;
        g_xs[((size_t)b * HW + p) * C_IN + c0 + tx] = __float2half_rn(sm[tx][ty + 8 * i]);
    }
}

// ---------------- kernels 5/6: fp16 mma.sync GEMM, 2-product weight split ----------------
// D = Wh*B + Wl*B. Per 32-k chunk: tiles Ah, Al, B; B fragment shared by both products.
// BM=BN=128, BK=32, 512 thr (16 warps, warp tile 64x16), 4-stage cp.async pipeline.
// MODE 0: Kb=384,  epi: bias+silu+modulate -> g_hs fp16
// MODE 1: Kb=1536, epi: bias+residual -> fp32 out
#define TILE_BYTES  10240            // 128 rows x 80 B (64 B data, conflict-free ldsm)
#define STAGE_BYTES (3 * TILE_BYTES) // Ah + Al + B
#define SMEM_BYTES  (4 * STAGE_BYTES) // 122880; epilogue reuse needs 67584
template <int MODE>
__global__ __launch_bounds__(512) void mma_gemm(const float* __restrict__ bias,
                                                const float* __restrict__ xres,
                                                float* __restrict__ out) {
    constexpr int Kb  = (MODE == 0) ? C_IN : CMID;
    constexpr int NCH = Kb / 32;

    extern __shared__ __align__(16) char smem[];
    const uint32_t sb = smem_u32(smem);

    const int t = threadIdx.x, lane = t & 31, warp = t >> 5;
    const int wm = warp & 1, wn = warp >> 1;
    const int b = blockIdx.z, bm = blockIdx.y * 128, bn = blockIdx.x * 128;

    const __half* __restrict__ Ag = (MODE == 0) ? g_w1s : g_w2s;
    const __half* __restrict__ Bg = ((MODE == 0) ? g_xs : g_hs) + (size_t)b * HW * Kb;

    const int lrow = t >> 2, lseg = t & 3;
    const __half* __restrict__ aptrH = Ag + (size_t)(bm + lrow) * 2 * Kb + lseg * 8;
    const __half* __restrict__ aptrL = aptrH + Kb;
    const __half* __restrict__ bptr  = Bg + (size_t)(bn + lrow) * Kb + lseg * 8;
    const uint32_t sts_off = lrow * 80 + lseg * 16;

    const uint32_t a_off = (uint32_t)((wm * 64 + (lane & 15)) * 80 + (lane >> 4) * 16);
    const uint32_t b_off = (uint32_t)((wn * 16 + (lane & 7) + ((lane >> 4) & 1) * 8) * 80
                                      + ((lane >> 3) & 1) * 16);

    float acc[4][2][4];
    #pragma unroll
    for (int i = 0; i < 4; i++)
        #pragma unroll
        for (int j = 0; j < 2; j++)
            #pragma unroll
            for (int q = 0; q < 4; q++) acc[i][j][q] = 0.f;

    auto issue = [&](int ch2, int buf) {
        if (ch2 < NCH) {
            int kk = ch2 * 32;
            CP_ASYNC16(sb + buf * STAGE_BYTES + sts_off, aptrH + kk);
            CP_ASYNC16(sb + buf * STAGE_BYTES + TILE_BYTES + sts_off, aptrL + kk);
            CP_ASYNC16(sb + buf * STAGE_BYTES + 2 * TILE_BYTES + sts_off, bptr + kk);
        }
        CP_COMMIT();
    };

    issue(0, 0);
    issue(1, 1);
    issue(2, 2);

    for (int ch = 0; ch < NCH; ch++) {
        CP_WAIT2();
        __syncthreads();
        issue(ch + 3, (ch + 3) & 3);          // overwrites buf used at ch-1: safe post-barrier

        const uint32_t saH = sb + (ch & 3) * STAGE_BYTES;
        const uint32_t saL = saH + TILE_BYTES;
        const uint32_t sbb = saH + 2 * TILE_BYTES;
        #pragma unroll
        for (int s16 = 0; s16 < 2; s16++) {
            uint32_t Bv[4], A[4][4];
            ldsm4(Bv, sbb + b_off + s16 * 32);
            #pragma unroll
            for (int mi = 0; mi < 4; mi++)
                ldsm4(A[mi], saH + a_off + mi * 1280 + s16 * 32);
            #pragma unroll
            for (int mi = 0; mi < 4; mi++) {
                mma16816(acc[mi][0], A[mi], Bv);
                mma16816(acc[mi][1], A[mi], Bv + 2);
            }
            #pragma unroll
            for (int mi = 0; mi < 4; mi++)
                ldsm4(A[mi], saL + a_off + mi * 1280 + s16 * 32);
            #pragma unroll
            for (int mi = 0; mi < 4; mi++) {
                mma16816(acc[mi][0], A[mi], Bv);
                mma16816(acc[mi][1], A[mi], Bv + 2);
            }
        }
    }
    __syncthreads();   // smem reused for epilogue transpose

    uint32_t* smt = (uint32_t*)smem;   // [128][132]
    if (MODE == 0) {
        float bsv[8], scv[8], shv[8];
        #pragma unroll
        for (int mi = 0; mi < 4; mi++) {
            #pragma unroll
            for (int hh = 0; hh < 2; hh++) {
                int m = bm + wm * 64 + mi * 16 + (lane >> 2) + hh * 8;
                bsv[mi * 2 + hh] = bias[m];
                scv[mi * 2 + hh] = 1.f + g_emb[(size_t)b * 2 * CMID + m];
                shv[mi * 2 + hh] = g_emb[(size_t)b * 2 * CMID + CMID + m];
            }
        }
        #pragma unroll
        for (int mi = 0; mi < 4; mi++) {
            #pragma unroll
            for (int nj = 0; nj < 2; nj++) {
                int n0 = wn * 16 + nj * 8 + 2 * (lane & 3);
                #pragma unroll
                for (int q = 0; q < 4; q++) {
                    int hh = q >> 1;
                    int mloc = wm * 64 + mi * 16 + (lane >> 2) + hh * 8;
                    int n = n0 + (q & 1);
                    float v = acc[mi][nj][q] + bsv[mi * 2 + hh];
                    float s = v / (1.f + __expf(-v));
                    float r = fmaf(s, scv[mi * 2 + hh], shv[mi * 2 + hh]);
                    smt[n * 132 + mloc] = (uint32_t)__half_as_ushort(__float2half_rn(r));
                }
            }
        }
        __syncthreads();
        const int n = t >> 2, mseg = (t & 3) * 32;
        const size_t rowb = ((size_t)b * HW + bn + n) * CMID;
        #pragma unroll
        for (int j = 0; j < 4; j++) {
            uint32_t w[8];
            #pragma unroll
            for (int q = 0; q < 8; q++) w[q] = smt[n * 132 + mseg + 8 * j + q];
            uint4 vh;
            vh.x = (w[0] & 0xFFFFu) | (w[1] << 16);
            vh.y = (w[2] & 0xFFFFu) | (w[3] << 16);
            vh.z = (w[4] & 0xFFFFu) | (w[5] << 16);
            vh.w = (w[6] & 0xFFFFu) | (w[7] << 16);
            *(uint4*)(g_hs + rowb + bm + mseg + 8 * j) = vh;
        }
    } else {
        #pragma unroll
        for (int mi = 0; mi < 4; mi++) {
            #pragma unroll
            for (int nj = 0; nj < 2; nj++) {
                int n0 = wn * 16 + nj * 8 + 2 * (lane & 3);
                #pragma unroll
                for (int q = 0; q < 4; q++) {
                    int mloc = wm * 64 + mi * 16 + (lane >> 2) + (q >> 1) * 8;
                    int n = n0 + (q & 1);
                    smt[mloc * 132 + n] = __float_as_uint(acc[mi][nj][q]);
                }
            }
        }
        __syncthreads();
        const int m = t >> 2, nseg = (t & 3) * 32;
        const float bs = bias[bm + m];
        const size_t rowb = ((size_t)(b * C_IN + bm + m)) * HW + bn + nseg;
        #pragma unroll
        for (int j = 0; j < 8; j++) {
            float4 xr = *(const float4*)&xres[rowb + 4 * j];
            float4 o;
            o.x = __uint_as_float(smt[m * 132 + nseg + 4 * j + 0]) + bs + xr.x;
            o.y = __uint_as_float(smt[m * 132 + nseg + 4 * j + 1]) + bs + xr.y;
            o.z = __uint_as_float(smt[m * 132 + nseg + 4 * j + 2]) + bs + xr.z;
            o.w = __uint_as_float(smt[m * 132 + nseg + 4 * j + 3]) + bs + xr.w;
            *(float4*)&out[rowb + 4 * j] = o;
        }
    }
}

// ---------------- launch ----------------
extern "C" void kernel_launch(void* const* d_in, const int* in_sizes, int n_in,
                              void* d_out, int out_size) {
    const float* x    = (const float*)d_in[0];
    const float* emb  = (const float*)d_in[1];
    const float* gn_w = (const float*)d_in[2];
    const float* gn_b = (const float*)d_in[3];
    const float* w1   = (const float*)d_in[4];
    const float* b1   = (const float*)d_in[5];
    const float* we   = (const float*)d_in[6];
    const float* be   = (const float*)d_in[7];
    const float* w2   = (const float*)d_in[8];
    const float* b2   = (const float*)d_in[9];
    float* out = (float*)d_out;

    cudaFuncSetAttribute(mma_gemm<0>, cudaFuncAttributeMaxDynamicSharedMemorySize, SMEM_BYTES);
    cudaFuncSetAttribute(mma_gemm<1>, cudaFuncAttributeMaxDynamicSharedMemorySize, SMEM_BYTES);

    gn_stats_kernel<<<BB * NGROUP, 256>>>(x, gn_w, gn_b);
    emb_gemm_kernel<<<dim3(BB, (2 * CMID) / 8), 256>>>(emb, we, be);
    prep_w_kernel<<<(CMID * C_IN + 255) / 256, 256>>>(w1, w2);
    prep_x_kernel<<<dim3(HW / 32, C_IN / 32, BB), 256>>>(x);
    mma_gemm<0><<<dim3(HW / 128, CMID / 128, BB), 512, SMEM_BYTES>>>(b1, nullptr, nullptr);
    mma_gemm<1><<<dim3(HW / 128, C_IN / 128, BB), 512, SMEM_BYTES>>>(b2, x, out);
}

// round 16
// speedup vs baseline: 2.6949x; 1.4763x over previous
#include <cuda_runtime.h>
#include <cuda_fp16.h>
#include <math.h>
#include <stdint.h>

// ---------------- problem constants ----------------
#define BB     16
#define C_IN   384
#define HW     1024
#define CMID   1536
#define EMB_N  1024
#define NGROUP 32
#define CPG    (C_IN / NGROUP)
#define GSIZE  (CPG * HW)

// ---------------- scratch (global bss) ----------------
__device__ float g_a[BB * C_IN];
__device__ float g_d[BB * C_IN];
__device__ float g_emb[BB * 2 * CMID];
// single fp16 weights + activations
__device__ __align__(16) __half g_w1h[CMID * C_IN];
__device__ __align__(16) __half g_w2h[C_IN * CMID];
__device__ __align__(16) __half g_xs[(size_t)BB * HW * C_IN];    // xn^T [b][p][c]
__device__ __align__(16) __half g_hs[(size_t)BB * HW * CMID];    // h^T  [b][p][c]

__device__ __forceinline__ uint32_t smem_u32(const void* p) {
    uint32_t a;
    asm("{ .reg .u64 t; cvta.to.shared.u64 t, %1; cvt.u32.u64 %0, t; }" : "=r"(a) : "l"(p));
    return a;
}
__device__ __forceinline__ void ldsm4(uint32_t* r, uint32_t addr) {
    asm volatile("ldmatrix.sync.aligned.m8n8.x4.shared.b16 {%0,%1,%2,%3}, [%4];"
                 : "=r"(r[0]), "=r"(r[1]), "=r"(r[2]), "=r"(r[3]) : "r"(addr));
}
__device__ __forceinline__ void mma16816(float* d, const uint32_t* a, const uint32_t* b) {
    asm volatile("mma.sync.aligned.m16n8k16.row.col.f32.f16.f16.f32 "
                 "{%0,%1,%2,%3}, {%4,%5,%6,%7}, {%8,%9}, {%0,%1,%2,%3};"
                 : "+f"(d[0]), "+f"(d[1]), "+f"(d[2]), "+f"(d[3])
                 : "r"(a[0]), "r"(a[1]), "r"(a[2]), "r"(a[3]), "r"(b[0]), "r"(b[1]));
}
#define CP_ASYNC16(dst, src) \
    asm volatile("cp.async.cg.shared.global [%0], [%1], 16;" :: "r"(dst), "l"(src) : "memory")
#define CP_COMMIT() asm volatile("cp.async.commit_group;" ::: "memory")
#define CP_WAIT2()  asm volatile("cp.async.wait_group 2;" ::: "memory")

// ---------------- kernel 1: groupnorm stats ----------------
__global__ __launch_bounds__(256) void gn_stats_kernel(const float* __restrict__ x,
                                                       const float* __restrict__ gn_w,
                                                       const float* __restrict__ gn_b) {
    int g = blockIdx.x, b = g / NGROUP, grp = g % NGROUP;
    const float4* base = (const float4*)(x + ((size_t)b * C_IN + grp * CPG) * HW);
    float s = 0.f, ss = 0.f;
    for (int i = threadIdx.x; i < GSIZE / 4; i += 256) {
        float4 v = base[i];
        s += v.x + v.y + v.z + v.w;
        ss += v.x * v.x + v.y * v.y + v.z * v.z + v.w * v.w;
    }
    for (int o = 16; o; o >>= 1) {
        s  += __shfl_down_sync(0xffffffffu, s, o);
        ss += __shfl_down_sync(0xffffffffu, ss, o);
    }
    __shared__ float rs[8], rss[8], smu, srstd;
    int warp = threadIdx.x >> 5, lane = threadIdx.x & 31;
    if (lane == 0) { rs[warp] = s; rss[warp] = ss; }
    __syncthreads();
    if (threadIdx.x == 0) {
        float ts = 0.f, tss = 0.f;
        #pragma unroll
        for (int w = 0; w < 8; w++) { ts += rs[w]; tss += rss[w]; }
        float mu = ts / (float)GSIZE;
        smu = mu;
        srstd = rsqrtf(tss / (float)GSIZE - mu * mu + 1e-5f);
    }
    __syncthreads();
    if (threadIdx.x < CPG) {
        int c = grp * CPG + threadIdx.x;
        float a = srstd * gn_w[c];
        g_a[b * C_IN + c] = a;
        g_d[b * C_IN + c] = gn_b[c] - smu * a;
    }
}

// ---------------- kernel 2: emb GEMM ----------------
__global__ __launch_bounds__(256) void emb_gemm_kernel(const float* __restrict__ emb,
                                                       const float* __restrict__ we,
                                                       const float* __restrict__ be) {
    int b = blockIdx.x, o = blockIdx.y * 8 + (threadIdx.x >> 5), lane = threadIdx.x & 31;
    __shared__ float4 semb[EMB_N / 4];
    const float4* er = (const float4*)(emb + (size_t)b * EMB_N);
    for (int i = threadIdx.x; i < EMB_N / 4; i += 256) semb[i] = er[i];
    __syncthreads();
    const float4* wr = (const float4*)(we + (size_t)o * EMB_N);
    float s = 0.f;
    #pragma unroll
    for (int i = lane; i < EMB_N / 4; i += 32) {
        float4 a = semb[i], w = wr[i];
        s += a.x * w.x + a.y * w.y + a.z * w.z + a.w * w.w;
    }
    for (int off = 16; off; off >>= 1) s += __shfl_down_sync(0xffffffffu, s, off);
    if (lane == 0) g_emb[(size_t)b * 2 * CMID + o] = s + be[o];
}

// ---------------- kernel 3: weights -> fp16 ----------------
__global__ __launch_bounds__(256) void prep_w_kernel(const float* __restrict__ w1,
                                                     const float* __restrict__ w2) {
    int i = blockIdx.x * 256 + threadIdx.x;
    if (i < CMID * C_IN) {
        g_w1h[i] = __float2half_rn(w1[i]);
        g_w2h[i] = __float2half_rn(w2[i]);
    }
}

// ---------------- kernel 4: xn^T fp16 (GN affine + transpose) ----------------
__global__ __launch_bounds__(256) void prep_x_kernel(const float* __restrict__ x) {
    __shared__ float sm[32][33];
    int p0 = blockIdx.x * 32, c0 = blockIdx.y * 32, b = blockIdx.z;
    int tx = threadIdx.x & 31, ty = threadIdx.x >> 5;
    #pragma unroll
    for (int i = 0; i < 4; i++) {
        int c = c0 + ty + 8 * i;
        float av = g_a[b * C_IN + c], dv = g_d[b * C_IN + c];
        sm[ty + 8 * i][tx] = fmaf(x[((size_t)b * C_IN + c) * HW + p0 + tx], av, dv);
    }
    __syncthreads();
    #pragma unroll
    for (int i = 0; i < 4; i++) {
        int p = p0 + ty + 8 * i;
        g_xs[((size_t)b * HW + p) * C_IN + c0 + tx] = __float2half_rn(sm[tx][ty + 8 * i]);
    }
}

// ---------------- kernels 5/6: single-fp16 mma.sync GEMM ----------------
// D = W*B (fp16 x fp16 -> fp32 accum). Per 32-k chunk: tiles A, B.
// BM=BN=128, BK=32, 512 thr (16 warps, warp tile 64x16), 4-stage cp.async pipeline.
// MODE 0: Kb=384,  epi: bias+silu+modulate -> g_hs fp16
// MODE 1: Kb=1536, epi: bias+residual -> fp32 out
#define TILE_BYTES  10240            // 128 rows x 80 B (64 B data, conflict-free ldsm)
#define STAGE_BYTES (2 * TILE_BYTES) // A + B
#define SMEM_BYTES  (4 * STAGE_BYTES) // 81920; epilogue reuse needs 67584
template <int MODE>
__global__ __launch_bounds__(512) void mma_gemm(const float* __restrict__ bias,
                                                const float* __restrict__ xres,
                                                float* __restrict__ out) {
    constexpr int Kb  = (MODE == 0) ? C_IN : CMID;
    constexpr int NCH = Kb / 32;

    extern __shared__ __align__(16) char smem[];
    const uint32_t sb = smem_u32(smem);

    const int t = threadIdx.x, lane = t & 31, warp = t >> 5;
    const int wm = warp & 1, wn = warp >> 1;
    const int b = blockIdx.z, bm = blockIdx.y * 128, bn = blockIdx.x * 128;

    const __half* __restrict__ Ag = (MODE == 0) ? g_w1h : g_w2h;
    const __half* __restrict__ Bg = ((MODE == 0) ? g_xs : g_hs) + (size_t)b * HW * Kb;

    const int lrow = t >> 2, lseg = t & 3;
    const __half* __restrict__ aptr = Ag + (size_t)(bm + lrow) * Kb + lseg * 8;
    const __half* __restrict__ bptr = Bg + (size_t)(bn + lrow) * Kb + lseg * 8;
    const uint32_t sts_off = lrow * 80 + lseg * 16;

    const uint32_t a_off = (uint32_t)((wm * 64 + (lane & 15)) * 80 + (lane >> 4) * 16);
    const uint32_t b_off = (uint32_t)((wn * 16 + (lane & 7) + ((lane >> 4) & 1) * 8) * 80
                                      + ((lane >> 3) & 1) * 16);

    float acc[4][2][4];
    #pragma unroll
    for (int i = 0; i < 4; i++)
        #pragma unroll
        for (int j = 0; j < 2; j++)
            #pragma unroll
            for (int q = 0; q < 4; q++) acc[i][j][q] = 0.f;

    auto issue = [&](int ch2, int buf) {
        if (ch2 < NCH) {
            int kk = ch2 * 32;
            CP_ASYNC16(sb + buf * STAGE_BYTES + sts_off, aptr + kk);
            CP_ASYNC16(sb + buf * STAGE_BYTES + TILE_BYTES + sts_off, bptr + kk);
        }
        CP_COMMIT();
    };

    issue(0, 0);
    issue(1, 1);
    issue(2, 2);

    for (int ch = 0; ch < NCH; ch++) {
        CP_WAIT2();
        __syncthreads();
        issue(ch + 3, (ch + 3) & 3);          // overwrites buf used at ch-1: safe post-barrier

        const uint32_t sa  = sb + (ch & 3) * STAGE_BYTES;
        const uint32_t sbb = sa + TILE_BYTES;
        #pragma unroll
        for (int s16 = 0; s16 < 2; s16++) {
            uint32_t Bv[4], A[4][4];
            ldsm4(Bv, sbb + b_off + s16 * 32);
            #pragma unroll
            for (int mi = 0; mi < 4; mi++)
                ldsm4(A[mi], sa + a_off + mi * 1280 + s16 * 32);
            #pragma unroll
            for (int mi = 0; mi < 4; mi++) {
                mma16816(acc[mi][0], A[mi], Bv);
                mma16816(acc[mi][1], A[mi], Bv + 2);
            }
        }
    }
    __syncthreads();   // smem reused for epilogue transpose

    uint32_t* smt = (uint32_t*)smem;   // [128][132]
    if (MODE == 0) {
        float bsv[8], scv[8], shv[8];
        #pragma unroll
        for (int mi = 0; mi < 4; mi++) {
            #pragma unroll
            for (int hh = 0; hh < 2; hh++) {
                int m = bm + wm * 64 + mi * 16 + (lane >> 2) + hh * 8;
                bsv[mi * 2 + hh] = bias[m];
                scv[mi * 2 + hh] = 1.f + g_emb[(size_t)b * 2 * CMID + m];
                shv[mi * 2 + hh] = g_emb[(size_t)b * 2 * CMID + CMID + m];
            }
        }
        #pragma unroll
        for (int mi = 0; mi < 4; mi++) {
            #pragma unroll
            for (int nj = 0; nj < 2; nj++) {
                int n0 = wn * 16 + nj * 8 + 2 * (lane & 3);
                #pragma unroll
                for (int q = 0; q < 4; q++) {
                    int hh = q >> 1;
                    int mloc = wm * 64 + mi * 16 + (lane >> 2) + hh * 8;
                    int n = n0 + (q & 1);
                    float v = acc[mi][nj][q] + bsv[mi * 2 + hh];
                    float s = v / (1.f + __expf(-v));
                    float r = fmaf(s, scv[mi * 2 + hh], shv[mi * 2 + hh]);
                    smt[n * 132 + mloc] = (uint32_t)__half_as_ushort(__float2half_rn(r));
                }
            }
        }
        __syncthreads();
        const int n = t >> 2, mseg = (t & 3) * 32;
        const size_t rowb = ((size_t)b * HW + bn + n) * CMID;
        #pragma unroll
        for (int j = 0; j < 4; j++) {
            uint32_t w[8];
            #pragma unroll
            for (int q = 0; q < 8; q++) w[q] = smt[n * 132 + mseg + 8 * j + q];
            uint4 vh;
            vh.x = (w[0] & 0xFFFFu) | (w[1] << 16);
            vh.y = (w[2] & 0xFFFFu) | (w[3] << 16);
            vh.z = (w[4] & 0xFFFFu) | (w[5] << 16);
            vh.w = (w[6] & 0xFFFFu) | (w[7] << 16);
            *(uint4*)(g_hs + rowb + bm + mseg + 8 * j) = vh;
        }
    } else {
        #pragma unroll
        for (int mi = 0; mi < 4; mi++) {
            #pragma unroll
            for (int nj = 0; nj < 2; nj++) {
                int n0 = wn * 16 + nj * 8 + 2 * (lane & 3);
                #pragma unroll
                for (int q = 0; q < 4; q++) {
                    int mloc = wm * 64 + mi * 16 + (lane >> 2) + (q >> 1) * 8;
                    int n = n0 + (q & 1);
                    smt[mloc * 132 + n] = __float_as_uint(acc[mi][nj][q]);
                }
            }
        }
        __syncthreads();
        const int m = t >> 2, nseg = (t & 3) * 32;
        const float bs = bias[bm + m];
        const size_t rowb = ((size_t)(b * C_IN + bm + m)) * HW + bn + nseg;
        #pragma unroll
        for (int j = 0; j < 8; j++) {
            float4 xr = *(const float4*)&xres[rowb + 4 * j];
            float4 o;
            o.x = __uint_as_float(smt[m * 132 + nseg + 4 * j + 0]) + bs + xr.x;
            o.y = __uint_as_float(smt[m * 132 + nseg + 4 * j + 1]) + bs + xr.y;
            o.z = __uint_as_float(smt[m * 132 + nseg + 4 * j + 2]) + bs + xr.z;
            o.w = __uint_as_float(smt[m * 132 + nseg + 4 * j + 3]) + bs + xr.w;
            *(float4*)&out[rowb + 4 * j] = o;
        }
    }
}

// ---------------- launch ----------------
extern "C" void kernel_launch(void* const* d_in, const int* in_sizes, int n_in,
                              void* d_out, int out_size) {
    const float* x    = (const float*)d_in[0];
    const float* emb  = (const float*)d_in[1];
    const float* gn_w = (const float*)d_in[2];
    const float* gn_b = (const float*)d_in[3];
    const float* w1   = (const float*)d_in[4];
    const float* b1   = (const float*)d_in[5];
    const float* we   = (const float*)d_in[6];
    const float* be   = (const float*)d_in[7];
    const float* w2   = (const float*)d_in[8];
    const float* b2   = (const float*)d_in[9];
    float* out = (float*)d_out;

    cudaFuncSetAttribute(mma_gemm<0>, cudaFuncAttributeMaxDynamicSharedMemorySize, SMEM_BYTES);
    cudaFuncSetAttribute(mma_gemm<1>, cudaFuncAttributeMaxDynamicSharedMemorySize, SMEM_BYTES);

    gn_stats_kernel<<<BB * NGROUP, 256>>>(x, gn_w, gn_b);
    emb_gemm_kernel<<<dim3(BB, (2 * CMID) / 8), 256>>>(emb, we, be);
    prep_w_kernel<<<(CMID * C_IN + 255) / 256, 256>>>(w1, w2);
    prep_x_kernel<<<dim3(HW / 32, C_IN / 32, BB), 256>>>(x);
    mma_gemm<0><<<dim3(HW / 128, CMID / 128, BB), 512, SMEM_BYTES>>>(b1, nullptr, nullptr);
    mma_gemm<1><<<dim3(HW / 128, C_IN / 128, BB), 512, SMEM_BYTES>>>(b2, x, out);
}